// round 14
// baseline (speedup 1.0000x reference)
#include <cuda_runtime.h>
#include <cuda_bf16.h>
#include <math.h>
#include <stdint.h>

#define B_  2
#define T_  1024
#define C_  768
#define L_  12
#define H_  12
#define V_  50257
#define D_  64
#define BT  (B_*T_)          // 2048
#define C3  (3*C_)           // 2304
#define C4  (4*C_)           // 3072

typedef __nv_bfloat16 bf16;

// ---------------- scratch (device globals) ----------------
__device__ float g_x  [BT*C_];
__device__ float g_logits_fb[(size_t)BT*V_];
__device__ float g_nll[BT];
__device__ int   g_valid[BT];

// split-bf16 activations
__device__ bf16 g_lnh[BT*C_],  g_lnl[BT*C_];
__device__ bf16 g_qkvh[BT*C3], g_qkvl[BT*C3];
__device__ bf16 g_yh[BT*C_],   g_yl[BT*C_];
__device__ bf16 g_fch[BT*C4],  g_fcl[BT*C4];

// split-bf16 weights
__device__ bf16 g_wqkv_h[(size_t)L_*C_*C3], g_wqkv_l[(size_t)L_*C_*C3];
__device__ bf16 g_wapr_h[(size_t)L_*C_*C_], g_wapr_l[(size_t)L_*C_*C_];
__device__ bf16 g_wfc_h [(size_t)L_*C_*C4], g_wfc_l [(size_t)L_*C_*C4];
__device__ bf16 g_wmp_h [(size_t)L_*C4*C_], g_wmp_l [(size_t)L_*C4*C_];
__device__ bf16 g_wte_h [(size_t)V_*C_],    g_wte_l [(size_t)V_*C_];

// ---------------- ptx helpers ----------------
__device__ __forceinline__ uint32_t smem_u32(const void* p) {
    uint32_t a;
    asm("{ .reg .u64 t; cvta.to.shared.u64 t, %1; cvt.u32.u64 %0, t; }" : "=r"(a) : "l"(p));
    return a;
}
template<int N> __device__ __forceinline__ void cp_wait() {
    asm volatile("cp.async.wait_group %0;" :: "n"(N) : "memory");
}
__device__ __forceinline__ void cp_commit() {
    asm volatile("cp.async.commit_group;" ::: "memory");
}
__device__ __forceinline__ void cp16(uint32_t dst, const void* src, int sz) {
    asm volatile("cp.async.cg.shared.global [%0], [%1], 16, %2;"
                 :: "r"(dst), "l"(src), "r"(sz) : "memory");
}
__device__ __forceinline__ void ldsm4(uint32_t* r, uint32_t a) {
    asm volatile("ldmatrix.sync.aligned.m8n8.x4.shared.b16 {%0,%1,%2,%3}, [%4];"
                 : "=r"(r[0]), "=r"(r[1]), "=r"(r[2]), "=r"(r[3]) : "r"(a));
}
__device__ __forceinline__ void ldsm2t(uint32_t* r, uint32_t a) {
    asm volatile("ldmatrix.sync.aligned.m8n8.x2.trans.shared.b16 {%0,%1}, [%2];"
                 : "=r"(r[0]), "=r"(r[1]) : "r"(a));
}
__device__ __forceinline__ void mma16816(float* d, const uint32_t* a, const uint32_t* b) {
    asm volatile("mma.sync.aligned.m16n8k16.row.col.f32.bf16.bf16.f32 "
                 "{%0,%1,%2,%3}, {%4,%5,%6,%7}, {%8,%9}, {%0,%1,%2,%3};"
                 : "+f"(d[0]), "+f"(d[1]), "+f"(d[2]), "+f"(d[3])
                 : "r"(a[0]), "r"(a[1]), "r"(a[2]), "r"(a[3]), "r"(b[0]), "r"(b[1]));
}
__device__ __forceinline__ uint32_t pack_bf2(float a, float b) {
    __nv_bfloat162 t = __floats2bfloat162_rn(a, b);
    return *(uint32_t*)&t;
}
__device__ __forceinline__ uint32_t pack2(bf16 a, bf16 b) {
    return (uint32_t)(*(uint16_t*)&a) | ((uint32_t)(*(uint16_t*)&b) << 16);
}

__device__ __forceinline__ float gelu_f(float x) {
    const float k = 0.7978845608028654f;
    float x3 = x * x * x;
    return 0.5f * x * (1.0f + tanhf(k * (x + 0.044715f * x3)));
}

// ---------------- conversion kernels (weights only, vectorized) ------------
__global__ void convert_split(const float* __restrict__ in, bf16* __restrict__ hi,
                              bf16* __restrict__ lo, int n4) {
    int i = blockIdx.x * blockDim.x + threadIdx.x;
    int stride = gridDim.x * blockDim.x;
    const float4* in4 = (const float4*)in;
    uint2* hi2 = (uint2*)hi;
    uint2* lo2 = (uint2*)lo;
    for (; i < n4; i += stride) {
        float4 v = in4[i];
        bf16 h0 = __float2bfloat16_rn(v.x), h1 = __float2bfloat16_rn(v.y);
        bf16 h2 = __float2bfloat16_rn(v.z), h3 = __float2bfloat16_rn(v.w);
        hi2[i] = make_uint2(pack2(h0, h1), pack2(h2, h3));
        lo2[i] = make_uint2(pack_bf2(v.x - __bfloat162float(h0), v.y - __bfloat162float(h1)),
                            pack_bf2(v.z - __bfloat162float(h2), v.w - __bfloat162float(h3)));
    }
}

// in: [K,N] row-major per layer -> out: [N,K] split, 64k x 32n tiles
__global__ void transpose_split(const float* __restrict__ in, bf16* __restrict__ hi,
                                bf16* __restrict__ lo, int K, int N) {
    int l = blockIdx.z;
    in += (size_t)l * K * N;
    hi += (size_t)l * K * N;
    lo += (size_t)l * K * N;
    __shared__ float t[64][33];
    int n0 = blockIdx.x * 32, k0 = blockIdx.y * 64;
    #pragma unroll
    for (int i = 0; i < 8; i++) {
        int k = threadIdx.y + i * 8;
        t[k][threadIdx.x] = in[(size_t)(k0 + k) * N + n0 + threadIdx.x];
    }
    __syncthreads();
    #pragma unroll
    for (int i = 0; i < 4; i++) {
        int n = threadIdx.y + i * 8;
        float a = t[2 * threadIdx.x][n], c = t[2 * threadIdx.x + 1][n];
        bf16 ha = __float2bfloat16_rn(a), hc = __float2bfloat16_rn(c);
        size_t o = (size_t)(n0 + n) * K + k0 + 2 * threadIdx.x;
        *(uint32_t*)(hi + o) = pack2(ha, hc);
        *(uint32_t*)(lo + o) = pack_bf2(a - __bfloat162float(ha), c - __bfloat162float(hc));
    }
}

// ---------------- HMMA split-bf16 GEMM (3-stage, BM=128) --------------------
#define FUSE_NONE 0
#define FUSE_RES  1
#define FUSE_GELU 2
#define GSTG 32768
#define GSM_TOTAL (3*GSTG)

__device__ __forceinline__ uint32_t swoff(int r, int c) {
    return (uint32_t)(r * 64 + ((c ^ ((r >> 1) & 3)) << 4));
}

__global__ __launch_bounds__(256)
void gemm_hmma(const bf16* __restrict__ Ah, const bf16* __restrict__ Al,
               const bf16* __restrict__ Bh, const bf16* __restrict__ Bl,
               const float* __restrict__ bias, const float* __restrict__ res,
               float* __restrict__ Cm, bf16* __restrict__ OutH, bf16* __restrict__ OutL,
               int M, int N, int K, int fuse) {
    extern __shared__ char smem[];
    uint32_t sb = smem_u32(smem);
    int tid = threadIdx.x, lane = tid & 31, w = tid >> 5;
    int wm0 = (w & 3) * 32, wn0 = (w >> 2) * 64;
    int m0 = blockIdx.y * 128, n0 = blockIdx.x * 128;

    float acc[2][8][4];
    #pragma unroll
    for (int i = 0; i < 2; i++)
        #pragma unroll
        for (int j = 0; j < 8; j++)
            #pragma unroll
            for (int k = 0; k < 4; k++) acc[i][j][k] = 0.f;

    int cr = tid >> 2, cb = tid & 3;
    int nch = K >> 5;
    int rowoff = (lane & 7) + ((lane >> 3) & 1) * 8;
    int cbh = lane >> 4;

    auto prefetch = [&](int ch, uint32_t base) {
        int k0 = ch * 32;
        #pragma unroll
        for (int i = 0; i < 2; i++) {
            int r = cr + i * 64;
            uint32_t d = swoff(r, cb);
            size_t ao = (size_t)(m0 + r) * K + k0 + cb * 8;
            cp16(base + d, Ah + ao, 16);
            cp16(base + 8192 + d, Al + ao, 16);
            int nr = n0 + r;
            int nc = nr < N ? nr : (N - 1);
            int sz = nr < N ? 16 : 0;
            size_t bo = (size_t)nc * K + k0 + cb * 8;
            cp16(base + 16384 + d, Bh + bo, sz);
            cp16(base + 24576 + d, Bl + bo, sz);
        }
    };

    prefetch(0, sb); cp_commit();
    if (nch > 1) prefetch(1, sb + GSTG);
    cp_commit();

    int stage = 0, pstage = 2;
    for (int ch = 0; ch < nch; ch++) {
        cp_wait<1>();
        __syncthreads();
        if (ch + 2 < nch) prefetch(ch + 2, sb + pstage * GSTG);
        cp_commit();

        uint32_t aB = sb + stage * GSTG;
        uint32_t bB = aB + 16384;
        #pragma unroll
        for (int ks = 0; ks < 2; ks++) {
            uint32_t ah[2][4], al[2][4];
            #pragma unroll
            for (int mi = 0; mi < 2; mi++) {
                int row = wm0 + mi * 16 + rowoff;
                uint32_t ad = aB + (uint32_t)(row * 64) +
                              (uint32_t)((((2 * ks + cbh) ^ ((row >> 1) & 3))) << 4);
                ldsm4(ah[mi], ad);
                ldsm4(al[mi], ad + 8192);
            }
            uint32_t bh[8][2], bl[8][2];
            #pragma unroll
            for (int nj = 0; nj < 4; nj++) {
                int row = wn0 + nj * 16 + rowoff;
                uint32_t bd = bB + (uint32_t)(row * 64) +
                              (uint32_t)((((2 * ks + cbh) ^ ((row >> 1) & 3))) << 4);
                uint32_t q[4];
                ldsm4(q, bd);
                bh[2 * nj][0] = q[0]; bh[2 * nj][1] = q[2];
                bh[2 * nj + 1][0] = q[1]; bh[2 * nj + 1][1] = q[3];
                ldsm4(q, bd + 8192);
                bl[2 * nj][0] = q[0]; bl[2 * nj][1] = q[2];
                bl[2 * nj + 1][0] = q[1]; bl[2 * nj + 1][1] = q[3];
            }
            #pragma unroll
            for (int mi = 0; mi < 2; mi++)
                #pragma unroll
                for (int ni = 0; ni < 8; ni++) {
                    mma16816(acc[mi][ni], ah[mi], bh[ni]);
                    mma16816(acc[mi][ni], ah[mi], bl[ni]);
                    mma16816(acc[mi][ni], al[mi], bh[ni]);
                }
        }
        stage = (stage == 2) ? 0 : stage + 1;
        pstage = (pstage == 2) ? 0 : pstage + 1;
    }

    int r0 = lane >> 2, c0 = (lane & 3) * 2;
    bool vec_ok = (n0 + 128 <= N) && ((N & 1) == 0);
    #pragma unroll
    for (int mi = 0; mi < 2; mi++) {
        #pragma unroll
        for (int ni = 0; ni < 8; ni++) {
            int gr = m0 + wm0 + mi * 16 + r0;
            int gc = n0 + wn0 + ni * 8 + c0;
            float v0 = acc[mi][ni][0], v1 = acc[mi][ni][1];
            float v2 = acc[mi][ni][2], v3 = acc[mi][ni][3];
            if (vec_ok) {
                if (bias) { float b0 = bias[gc], b1 = bias[gc + 1]; v0 += b0; v1 += b1; v2 += b0; v3 += b1; }
                if (fuse == FUSE_RES) {
                    const float* r1p = res + (size_t)gr * N + gc;
                    const float* r2p = res + (size_t)(gr + 8) * N + gc;
                    v0 += r1p[0]; v1 += r1p[1]; v2 += r2p[0]; v3 += r2p[1];
                } else if (fuse == FUSE_GELU) {
                    v0 = gelu_f(v0); v1 = gelu_f(v1); v2 = gelu_f(v2); v3 = gelu_f(v3);
                }
                if (OutH) {
                    bf16 h0 = __float2bfloat16_rn(v0), h1 = __float2bfloat16_rn(v1);
                    bf16 h2 = __float2bfloat16_rn(v2), h3 = __float2bfloat16_rn(v3);
                    *(uint32_t*)(OutH + (size_t)gr * N + gc)       = pack2(h0, h1);
                    *(uint32_t*)(OutH + (size_t)(gr + 8) * N + gc) = pack2(h2, h3);
                    *(uint32_t*)(OutL + (size_t)gr * N + gc)       = pack_bf2(v0 - __bfloat162float(h0), v1 - __bfloat162float(h1));
                    *(uint32_t*)(OutL + (size_t)(gr + 8) * N + gc) = pack_bf2(v2 - __bfloat162float(h2), v3 - __bfloat162float(h3));
                } else {
                    *(float2*)(Cm + (size_t)gr * N + gc)       = make_float2(v0, v1);
                    *(float2*)(Cm + (size_t)(gr + 8) * N + gc) = make_float2(v2, v3);
                }
            } else {
                if (gc < N) {
                    float b0 = bias ? bias[gc] : 0.f;
                    float a0 = v0 + b0, a2 = v2 + b0;
                    if (fuse == FUSE_RES) { a0 += res[(size_t)gr * N + gc]; a2 += res[(size_t)(gr + 8) * N + gc]; }
                    else if (fuse == FUSE_GELU) { a0 = gelu_f(a0); a2 = gelu_f(a2); }
                    Cm[(size_t)gr * N + gc] = a0;
                    Cm[(size_t)(gr + 8) * N + gc] = a2;
                }
                if (gc + 1 < N) {
                    float b1 = bias ? bias[gc + 1] : 0.f;
                    float a1 = v1 + b1, a3 = v3 + b1;
                    if (fuse == FUSE_RES) { a1 += res[(size_t)gr * N + gc + 1]; a3 += res[(size_t)(gr + 8) * N + gc + 1]; }
                    else if (fuse == FUSE_GELU) { a1 = gelu_f(a1); a3 = gelu_f(a3); }
                    Cm[(size_t)gr * N + gc + 1] = a1;
                    Cm[(size_t)(gr + 8) * N + gc + 1] = a3;
                }
            }
        }
    }
}

// ---------------- HMMA split-bf16 GEMM (BM=64 variant, N%128==0) ------------
#define G64STG 24576
#define G64_TOTAL (3*G64STG)

__global__ __launch_bounds__(256)
void gemm_hmma64(const bf16* __restrict__ Ah, const bf16* __restrict__ Al,
                 const bf16* __restrict__ Bh, const bf16* __restrict__ Bl,
                 const float* __restrict__ bias, const float* __restrict__ res,
                 float* __restrict__ Cm, int M, int N, int K, int fuse) {
    extern __shared__ char smem[];
    uint32_t sb = smem_u32(smem);
    int tid = threadIdx.x, lane = tid & 31, w = tid >> 5;
    int wm0 = (w & 3) * 16, wn0 = (w >> 2) * 64;
    int m0 = blockIdx.y * 64, n0 = blockIdx.x * 128;

    float acc[8][4];
    #pragma unroll
    for (int j = 0; j < 8; j++)
        #pragma unroll
        for (int k = 0; k < 4; k++) acc[j][k] = 0.f;

    int cr = tid >> 2, cb = tid & 3;
    int nch = K >> 5;
    int rowoff = (lane & 7) + ((lane >> 3) & 1) * 8;
    int cbh = lane >> 4;

    auto prefetch = [&](int ch, uint32_t base) {
        int k0 = ch * 32;
        {
            int r = cr;
            uint32_t d = swoff(r, cb);
            size_t ao = (size_t)(m0 + r) * K + k0 + cb * 8;
            cp16(base + d, Ah + ao, 16);
            cp16(base + 4096 + d, Al + ao, 16);
        }
        #pragma unroll
        for (int i = 0; i < 2; i++) {
            int r = cr + i * 64;
            uint32_t d = swoff(r, cb);
            size_t bo = (size_t)(n0 + r) * K + k0 + cb * 8;
            cp16(base + 8192 + d, Bh + bo, 16);
            cp16(base + 16384 + d, Bl + bo, 16);
        }
    };

    prefetch(0, sb); cp_commit();
    if (nch > 1) prefetch(1, sb + G64STG);
    cp_commit();

    int stage = 0, pstage = 2;
    for (int ch = 0; ch < nch; ch++) {
        cp_wait<1>();
        __syncthreads();
        if (ch + 2 < nch) prefetch(ch + 2, sb + pstage * G64STG);
        cp_commit();

        uint32_t aB = sb + stage * G64STG;
        uint32_t bB = aB + 8192;
        #pragma unroll
        for (int ks = 0; ks < 2; ks++) {
            uint32_t ah[4], al[4];
            {
                int row = wm0 + rowoff;
                uint32_t ad = aB + (uint32_t)(row * 64) +
                              (uint32_t)((((2 * ks + cbh) ^ ((row >> 1) & 3))) << 4);
                ldsm4(ah, ad);
                ldsm4(al, ad + 4096);
            }
            uint32_t bh[8][2], bl[8][2];
            #pragma unroll
            for (int nj = 0; nj < 4; nj++) {
                int row = wn0 + nj * 16 + rowoff;
                uint32_t bd = bB + (uint32_t)(row * 64) +
                              (uint32_t)((((2 * ks + cbh) ^ ((row >> 1) & 3))) << 4);
                uint32_t q[4];
                ldsm4(q, bd);
                bh[2 * nj][0] = q[0]; bh[2 * nj][1] = q[2];
                bh[2 * nj + 1][0] = q[1]; bh[2 * nj + 1][1] = q[3];
                ldsm4(q, bd + 8192);
                bl[2 * nj][0] = q[0]; bl[2 * nj][1] = q[2];
                bl[2 * nj + 1][0] = q[1]; bl[2 * nj + 1][1] = q[3];
            }
            #pragma unroll
            for (int ni = 0; ni < 8; ni++) {
                mma16816(acc[ni], ah, bh[ni]);
                mma16816(acc[ni], ah, bl[ni]);
                mma16816(acc[ni], al, bh[ni]);
            }
        }
        stage = (stage == 2) ? 0 : stage + 1;
        pstage = (pstage == 2) ? 0 : pstage + 1;
    }

    int r0 = lane >> 2, c0 = (lane & 3) * 2;
    #pragma unroll
    for (int ni = 0; ni < 8; ni++) {
        int gr = m0 + wm0 + r0;
        int gc = n0 + wn0 + ni * 8 + c0;
        float v0 = acc[ni][0], v1 = acc[ni][1];
        float v2 = acc[ni][2], v3 = acc[ni][3];
        if (bias) { float b0 = bias[gc], b1 = bias[gc + 1]; v0 += b0; v1 += b1; v2 += b0; v3 += b1; }
        if (fuse == FUSE_RES) {
            const float* r1p = res + (size_t)gr * N + gc;
            const float* r2p = res + (size_t)(gr + 8) * N + gc;
            v0 += r1p[0]; v1 += r1p[1]; v2 += r2p[0]; v3 += r2p[1];
        } else if (fuse == FUSE_GELU) {
            v0 = gelu_f(v0); v1 = gelu_f(v1); v2 = gelu_f(v2); v3 = gelu_f(v3);
        }
        *(float2*)(Cm + (size_t)gr * N + gc)       = make_float2(v0, v1);
        *(float2*)(Cm + (size_t)(gr + 8) * N + gc) = make_float2(v2, v3);
    }
}

// ---------------- flash attention (128-row Q tiles, 8 warps) ----------------
// Per-warp math identical to the 64-row version (same 16 rows per warp, same
// chunk order) -> bit-identical output; KV staging amortized over 2x rows.
#define FPAD 72
#define FARR 9216
#define FSTG (4*FARR)
#define FSM_TOTAL (2*FSTG)
#define QROWS 128
__global__ __launch_bounds__(256)
void flash_attn(const bf16* __restrict__ qkvh, const bf16* __restrict__ qkvl,
                bf16* __restrict__ yh, bf16* __restrict__ yl) {
    extern __shared__ char fsm[];
    uint32_t sbase = smem_u32(fsm);
    int qt = gridDim.x - 1 - blockIdx.x;       // long tiles first
    int bh = blockIdx.y;
    int b = bh / H_, h = bh % H_;
    int tid = threadIdx.x, w = tid >> 5, lane = tid & 31;
    int g = lane >> 2, tg = lane & 3;
    int t0 = qt * QROWS;
    int row = t0 + w * 16 + g;
    int wmax = t0 + w * 16 + 15;               // warp's highest q row
    size_t grA = (size_t)(b * T_ + row) * C3 + h * D_;
    size_t grB = grA + (size_t)8 * C3;

    auto pf = [&](int st, uint32_t base) {
        int s0 = st * 64;
        #pragma unroll
        for (int i = 0; i < 4; i++) {
            int e = tid + i * 256;               // 0..1023
            int r = (e >> 3) & 63, j = e & 7;
            int isV = (e >= 512);
            size_t gsrc = (size_t)(b * T_ + s0 + r) * C3 + C_ + (isV ? C_ : 0) + h * D_ + j * 8;
            uint32_t d = base + (uint32_t)(isV ? 2 * FARR : 0) + (uint32_t)(r * 144 + j * 16);
            cp16(d, qkvh + gsrc, 16);
            cp16(d + FARR, qkvl + gsrc, 16);
        }
    };

    uint32_t qah[4][4], qal[4][4];
    #pragma unroll
    for (int kk = 0; kk < 4; kk++) {
        int k = kk * 16 + tg * 2;
        qah[kk][0] = *(const uint32_t*)(qkvh + grA + k);
        qah[kk][1] = *(const uint32_t*)(qkvh + grB + k);
        qah[kk][2] = *(const uint32_t*)(qkvh + grA + k + 8);
        qah[kk][3] = *(const uint32_t*)(qkvh + grB + k + 8);
        qal[kk][0] = *(const uint32_t*)(qkvl + grA + k);
        qal[kk][1] = *(const uint32_t*)(qkvl + grB + k);
        qal[kk][2] = *(const uint32_t*)(qkvl + grA + k + 8);
        qal[kk][3] = *(const uint32_t*)(qkvl + grB + k + 8);
    }

    pf(0, sbase);
    cp_commit();

    float O[8][4];
    #pragma unroll
    for (int i = 0; i < 8; i++)
        #pragma unroll
        for (int j = 0; j < 4; j++) O[i][j] = 0.f;
    float m0 = -1e30f, m1 = -1e30f, l0 = 0.f, l1 = 0.f;

    int nst = (t0 + QROWS - 1) / 64 + 1;       // kv chunks for this q tile
    for (int st = 0; st < nst; st++) {
        int s0 = st * 64;
        cp_wait<0>();
        __syncthreads();
        if (st + 1 < nst) { pf(st + 1, sbase + ((st + 1) & 1) * FSTG); cp_commit(); }

        if (s0 <= wmax) {
            uint32_t stg = sbase + (st & 1) * FSTG;
            const bf16* kh = (const bf16*)(fsm + (st & 1) * FSTG);
            const bf16* kl = kh + FARR / 2;

            float S[8][4];
            #pragma unroll
            for (int nf = 0; nf < 8; nf++) {
                S[nf][0] = S[nf][1] = S[nf][2] = S[nf][3] = 0.f;
                int n = nf * 8 + g;
                #pragma unroll
                for (int kk = 0; kk < 4; kk++) {
                    int k = kk * 16 + tg * 2;
                    uint32_t bfr[2], bfl[2];
                    bfr[0] = *(const uint32_t*)&kh[n * FPAD + k];
                    bfr[1] = *(const uint32_t*)&kh[n * FPAD + k + 8];
                    bfl[0] = *(const uint32_t*)&kl[n * FPAD + k];
                    bfl[1] = *(const uint32_t*)&kl[n * FPAD + k + 8];
                    mma16816(S[nf], qah[kk], bfr);
                    mma16816(S[nf], qah[kk], bfl);
                    mma16816(S[nf], qal[kk], bfr);
                }
            }

            bool diag = (s0 + 63 > wmax - 15);   // chunk reaches warp's diagonal
            #pragma unroll
            for (int nf = 0; nf < 8; nf++) {
                int cbase = s0 + nf * 8 + tg * 2;
                #pragma unroll
                for (int j = 0; j < 4; j++) {
                    S[nf][j] *= 0.125f;
                    if (diag) {
                        int cc = cbase + (j & 1);
                        int rr = row + (j >> 1) * 8;
                        if (cc > rr) S[nf][j] = -1e30f;
                    }
                }
            }

            float rm0 = -1e30f, rm1 = -1e30f;
            #pragma unroll
            for (int nf = 0; nf < 8; nf++) {
                rm0 = fmaxf(rm0, fmaxf(S[nf][0], S[nf][1]));
                rm1 = fmaxf(rm1, fmaxf(S[nf][2], S[nf][3]));
            }
            rm0 = fmaxf(rm0, __shfl_xor_sync(0xffffffffu, rm0, 1));
            rm0 = fmaxf(rm0, __shfl_xor_sync(0xffffffffu, rm0, 2));
            rm1 = fmaxf(rm1, __shfl_xor_sync(0xffffffffu, rm1, 1));
            rm1 = fmaxf(rm1, __shfl_xor_sync(0xffffffffu, rm1, 2));
            float mn0 = fmaxf(m0, rm0), mn1 = fmaxf(m1, rm1);
            float cr0 = __expf(m0 - mn0), cr1 = __expf(m1 - mn1);
            m0 = mn0; m1 = mn1;

            uint32_t ph[8][2], pl[8][2];
            float ls0 = 0.f, ls1 = 0.f;
            #pragma unroll
            for (int nf = 0; nf < 8; nf++) {
                float p0 = __expf(S[nf][0] - m0), p1 = __expf(S[nf][1] - m0);
                float p2 = __expf(S[nf][2] - m1), p3 = __expf(S[nf][3] - m1);
                ls0 += p0 + p1; ls1 += p2 + p3;
                bf16 h0 = __float2bfloat16_rn(p0), h1 = __float2bfloat16_rn(p1);
                bf16 h2 = __float2bfloat16_rn(p2), h3 = __float2bfloat16_rn(p3);
                ph[nf][0] = pack2(h0, h1);
                ph[nf][1] = pack2(h2, h3);
                pl[nf][0] = pack_bf2(p0 - __bfloat162float(h0), p1 - __bfloat162float(h1));
                pl[nf][1] = pack_bf2(p2 - __bfloat162float(h2), p3 - __bfloat162float(h3));
            }
            l0 = l0 * cr0 + ls0;
            l1 = l1 * cr1 + ls1;
            #pragma unroll
            for (int nf = 0; nf < 8; nf++) {
                O[nf][0] *= cr0; O[nf][1] *= cr0;
                O[nf][2] *= cr1; O[nf][3] *= cr1;
            }

            uint32_t vhB = stg + 2 * FARR;
            int lrow = lane & 15;
            #pragma unroll
            for (int kk = 0; kk < 4; kk++) {
                uint32_t pah[4] = { ph[2*kk][0], ph[2*kk][1], ph[2*kk+1][0], ph[2*kk+1][1] };
                uint32_t pal[4] = { pl[2*kk][0], pl[2*kk][1], pl[2*kk+1][0], pl[2*kk+1][1] };
                uint32_t rbase = vhB + (uint32_t)((kk * 16 + lrow) * 144);
                #pragma unroll
                for (int nf = 0; nf < 8; nf++) {
                    uint32_t addr = rbase + (uint32_t)(nf * 16);
                    uint32_t vbh[2], vbl[2];
                    ldsm2t(vbh, addr);
                    ldsm2t(vbl, addr + FARR);
                    mma16816(O[nf], pah, vbh);
                    mma16816(O[nf], pah, vbl);
                    mma16816(O[nf], pal, vbh);
                }
            }
        }
    }

    l0 += __shfl_xor_sync(0xffffffffu, l0, 1);
    l0 += __shfl_xor_sync(0xffffffffu, l0, 2);
    l1 += __shfl_xor_sync(0xffffffffu, l1, 1);
    l1 += __shfl_xor_sync(0xffffffffu, l1, 2);
    float inv0 = 1.0f / l0, inv1 = 1.0f / l1;
    size_t yo0 = (size_t)(b * T_ + row) * C_ + h * D_;
    size_t yo1 = yo0 + (size_t)8 * C_;
    #pragma unroll
    for (int nf = 0; nf < 8; nf++) {
        int d = nf * 8 + tg * 2;
        float v0 = O[nf][0] * inv0, v1 = O[nf][1] * inv0;
        float v2 = O[nf][2] * inv1, v3 = O[nf][3] * inv1;
        bf16 h0 = __float2bfloat16_rn(v0), h1 = __float2bfloat16_rn(v1);
        bf16 h2 = __float2bfloat16_rn(v2), h3 = __float2bfloat16_rn(v3);
        *(uint32_t*)(yh + yo0 + d) = pack2(h0, h1);
        *(uint32_t*)(yh + yo1 + d) = pack2(h2, h3);
        *(uint32_t*)(yl + yo0 + d) = pack_bf2(v0 - __bfloat162float(h0), v1 - __bfloat162float(h1));
        *(uint32_t*)(yl + yo1 + d) = pack_bf2(v2 - __bfloat162float(h2), v3 - __bfloat162float(h3));
    }
}

// ---------------- embedding (vectorized) ----------------
__global__ void embed_k(const int* __restrict__ idx, const float* __restrict__ wte,
                        const float* __restrict__ wpe, float* __restrict__ x) {
    int row = blockIdx.x;
    int t = row % T_;
    int tok = idx[row];
    const float4* pe = (const float4*)(wpe + (size_t)t * C_);
    const float4* pw = (const float4*)(wte + (size_t)tok * C_);
    float4* po = (float4*)(x + (size_t)row * C_);
    int i = threadIdx.x;
    float4 a = pw[i], c = pe[i];
    po[i] = make_float4(a.x + c.x, a.y + c.y, a.z + c.z, a.w + c.w);
}

// ---------------- layernorm -> split bf16 (192 thr, float4, 1-pass) --------
__global__ __launch_bounds__(192)
void layernorm_split(const float* __restrict__ x, const float* __restrict__ w,
                     const float* __restrict__ b, bf16* __restrict__ oh,
                     bf16* __restrict__ ol) {
    int row = blockIdx.x;
    int tid = threadIdx.x;
    const float4* px = (const float4*)(x + (size_t)row * C_);
    float4 v = px[tid];
    float s = v.x + v.y + v.z + v.w;
    float q = v.x * v.x + v.y * v.y + v.z * v.z + v.w * v.w;
    #pragma unroll
    for (int o = 16; o; o >>= 1) {
        s += __shfl_xor_sync(0xffffffffu, s, o);
        q += __shfl_xor_sync(0xffffffffu, q, o);
    }
    __shared__ float ss[6], qq[6];
    if ((tid & 31) == 0) { ss[tid >> 5] = s; qq[tid >> 5] = q; }
    __syncthreads();
    s = ss[0] + ss[1] + ss[2] + ss[3] + ss[4] + ss[5];
    q = qq[0] + qq[1] + qq[2] + qq[3] + qq[4] + qq[5];
    float mean = s * (1.0f / C_);
    float var = q * (1.0f / C_) - mean * mean;
    float rstd = rsqrtf(var + 1e-5f);

    float4 w4 = ((const float4*)w)[tid];
    float4 b4 = ((const float4*)b)[tid];
    float o0 = (v.x - mean) * rstd * w4.x + b4.x;
    float o1 = (v.y - mean) * rstd * w4.y + b4.y;
    float o2 = (v.z - mean) * rstd * w4.z + b4.z;
    float o3 = (v.w - mean) * rstd * w4.w + b4.w;
    bf16 h0 = __float2bfloat16_rn(o0), h1 = __float2bfloat16_rn(o1);
    bf16 h2 = __float2bfloat16_rn(o2), h3 = __float2bfloat16_rn(o3);
    ((uint2*)(oh + (size_t)row * C_))[tid] = make_uint2(pack2(h0, h1), pack2(h2, h3));
    ((uint2*)(ol + (size_t)row * C_))[tid] =
        make_uint2(pack_bf2(o0 - __bfloat162float(h0), o1 - __bfloat162float(h1)),
                   pack_bf2(o2 - __bfloat162float(h2), o3 - __bfloat162float(h3)));
}

// ---------------- loss: single-pass online logsumexp ----------------
__global__ void loss_rows(const float* __restrict__ logits, const int* __restrict__ targets,
                          float* __restrict__ nll, int* __restrict__ valid) {
    int row = blockIdx.x;
    const float* p = logits + (size_t)row * V_;
    int tid = threadIdx.x;

    int pre = ((16 - (int)(((uintptr_t)p) & 15)) & 15) >> 2;
    if (pre > V_) pre = V_;
    const float4* p4 = (const float4*)(p + pre);
    int n4 = (V_ - pre) >> 2;
    int tail = pre + n4 * 4;

    float m = -INFINITY, s = 0.f;
    auto upd = [&](float v) {
        if (v <= m) s += __expf(v - m);
        else { s = s * __expf(m - v) + 1.0f; m = v; }
    };
    if (tid < pre) upd(p[tid]);
    for (int i = tid; i < n4; i += 256) {
        float4 v = p4[i];
        upd(v.x); upd(v.y); upd(v.z); upd(v.w);
    }
    for (int i = tail + tid; i < V_; i += 256) upd(p[i]);

    __shared__ float rm[256], rs[256];
    rm[tid] = m; rs[tid] = s; __syncthreads();
    for (int off = 128; off > 0; off >>= 1) {
        if (tid < off) {
            float m2 = rm[tid + off], s2 = rs[tid + off];
            float mm = fmaxf(rm[tid], m2);
            rs[tid] = rs[tid] * __expf(rm[tid] - mm) + s2 * __expf(m2 - mm);
            rm[tid] = mm;
        }
        __syncthreads();
    }

    if (tid == 0) {
        int t = targets[row];
        if (t != -1) {
            nll[row] = -(p[t] - rm[0] - logf(rs[0]));
            valid[row] = 1;
        } else {
            nll[row] = 0.f;
            valid[row] = 0;
        }
    }
}

__global__ void finalize_loss(const float* __restrict__ nll, const int* __restrict__ valid,
                              float* out, int loss_idx) {
    __shared__ float red[256];
    __shared__ int cnt[256];
    int tid = threadIdx.x;
    float s = 0.f; int c = 0;
    for (int i = tid; i < BT; i += 256) { s += nll[i]; c += valid[i]; }
    red[tid] = s; cnt[tid] = c; __syncthreads();
    for (int off = 128; off > 0; off >>= 1) {
        if (tid < off) { red[tid] += red[tid + off]; cnt[tid] += cnt[tid + off]; }
        __syncthreads();
    }
    if (tid == 0) {
        int v = cnt[0]; if (v < 1) v = 1;
        out[loss_idx] = red[0] / (float)v;
    }
}

// ---------------- host launcher ----------------
extern "C" void kernel_launch(void* const* d_in, const int* in_sizes, int n_in,
                              void* d_out, int out_size) {
    const int*   idx     = (const int*)  d_in[0];
    const int*   targets = (const int*)  d_in[1];
    const float* wte     = (const float*)d_in[2];
    const float* wpe     = (const float*)d_in[3];
    const float* ln1_w   = (const float*)d_in[4];
    const float* ln1_b   = (const float*)d_in[5];
    const float* attn_w  = (const float*)d_in[6];
    const float* attn_b  = (const float*)d_in[7];
    const float* aproj_w = (const float*)d_in[8];
    const float* aproj_b = (const float*)d_in[9];
    const float* ln2_w   = (const float*)d_in[10];
    const float* ln2_b   = (const float*)d_in[11];
    const float* fc_w    = (const float*)d_in[12];
    const float* fc_b    = (const float*)d_in[13];
    const float* mproj_w = (const float*)d_in[14];
    const float* mproj_b = (const float*)d_in[15];
    const float* lnf_w   = (const float*)d_in[16];
    const float* lnf_b   = (const float*)d_in[17];

    float *px, *pfb, *pnll;
    int *pvalid;
    bf16 *plnh, *plnl, *pqkvh, *pqkvl, *pyh, *pyl, *pfch, *pfcl;
    bf16 *pwqh, *pwql, *pwah, *pwal, *pwfh, *pwfl, *pwmh, *pwml, *pteh, *ptel;
    cudaGetSymbolAddress((void**)&px,    g_x);
    cudaGetSymbolAddress((void**)&pfb,   g_logits_fb);
    cudaGetSymbolAddress((void**)&pnll,  g_nll);
    cudaGetSymbolAddress((void**)&pvalid,g_valid);
    cudaGetSymbolAddress((void**)&plnh,  g_lnh);
    cudaGetSymbolAddress((void**)&plnl,  g_lnl);
    cudaGetSymbolAddress((void**)&pqkvh, g_qkvh);
    cudaGetSymbolAddress((void**)&pqkvl, g_qkvl);
    cudaGetSymbolAddress((void**)&pyh,   g_yh);
    cudaGetSymbolAddress((void**)&pyl,   g_yl);
    cudaGetSymbolAddress((void**)&pfch,  g_fch);
    cudaGetSymbolAddress((void**)&pfcl,  g_fcl);
    cudaGetSymbolAddress((void**)&pwqh,  g_wqkv_h);
    cudaGetSymbolAddress((void**)&pwql,  g_wqkv_l);
    cudaGetSymbolAddress((void**)&pwah,  g_wapr_h);
    cudaGetSymbolAddress((void**)&pwal,  g_wapr_l);
    cudaGetSymbolAddress((void**)&pwfh,  g_wfc_h);
    cudaGetSymbolAddress((void**)&pwfl,  g_wfc_l);
    cudaGetSymbolAddress((void**)&pwmh,  g_wmp_h);
    cudaGetSymbolAddress((void**)&pwml,  g_wmp_l);
    cudaGetSymbolAddress((void**)&pteh,  g_wte_h);
    cudaGetSymbolAddress((void**)&ptel,  g_wte_l);

    cudaFuncSetAttribute(gemm_hmma,   cudaFuncAttributeMaxDynamicSharedMemorySize, GSM_TOTAL);
    cudaFuncSetAttribute(gemm_hmma64, cudaFuncAttributeMaxDynamicSharedMemorySize, G64_TOTAL);
    cudaFuncSetAttribute(flash_attn,  cudaFuncAttributeMaxDynamicSharedMemorySize, FSM_TOTAL);

    static cudaStream_t s2 = nullptr;
    static cudaEvent_t  ev_fork = nullptr, ev_join = nullptr;
    if (!s2) {
        cudaStreamCreateWithFlags(&s2, cudaStreamNonBlocking);
        cudaEventCreateWithFlags(&ev_fork, cudaEventDisableTiming);
        cudaEventCreateWithFlags(&ev_join, cudaEventDisableTiming);
    }

    const long long BTV = (long long)BT * V_;
    float* logits = ((long long)out_size >= BTV) ? (float*)d_out : pfb;

    dim3 tb(32, 8);

    cudaEventRecord(ev_fork, 0);
    cudaStreamWaitEvent(s2, ev_fork, 0);
    transpose_split<<<dim3(C_ / 32, C_ / 64, L_), tb, 0, s2>>>(aproj_w, pwah, pwal, C_, C_);
    transpose_split<<<dim3(C4 / 32, C_ / 64, L_), tb, 0, s2>>>(fc_w,    pwfh, pwfl, C_, C4);
    transpose_split<<<dim3(C_ / 32, C4 / 64, L_), tb, 0, s2>>>(mproj_w, pwmh, pwml, C4, C_);
    convert_split<<<4096, 256, 0, s2>>>(wte, pteh, ptel, (V_ * C_) / 4);
    cudaEventRecord(ev_join, s2);

    transpose_split<<<dim3(C3 / 32, C_ / 64, L_), tb>>>(attn_w, pwqh, pwql, C_, C3);
    embed_k<<<BT, 192>>>(idx, wte, wpe, px);

    for (int l = 0; l < L_; l++) {
        layernorm_split<<<BT, 192>>>(px, ln1_w + (size_t)l * C_, ln1_b + (size_t)l * C_, plnh, plnl);
        gemm_hmma<<<dim3(C3 / 128, BT / 128), 256, GSM_TOTAL>>>(
            plnh, plnl, pwqh + (size_t)l * C_ * C3, pwql + (size_t)l * C_ * C3,
            attn_b + (size_t)l * C3, nullptr, nullptr, pqkvh, pqkvl, BT, C3, C_, FUSE_NONE);

        flash_attn<<<dim3(T_ / QROWS, B_ * H_), 256, FSM_TOTAL>>>(pqkvh, pqkvl, pyh, pyl);

        if (l == 0) cudaStreamWaitEvent(0, ev_join, 0);

        gemm_hmma64<<<dim3(C_ / 128, BT / 64), 256, G64_TOTAL>>>(
            pyh, pyl, pwah + (size_t)l * C_ * C_, pwal + (size_t)l * C_ * C_,
            aproj_b + (size_t)l * C_, px, px, BT, C_, C_, FUSE_RES);

        layernorm_split<<<BT, 192>>>(px, ln2_w + (size_t)l * C_, ln2_b + (size_t)l * C_, plnh, plnl);
        gemm_hmma<<<dim3(C4 / 128, BT / 128), 256, GSM_TOTAL>>>(
            plnh, plnl, pwfh + (size_t)l * C_ * C4, pwfl + (size_t)l * C_ * C4,
            fc_b + (size_t)l * C4, nullptr, nullptr, pfch, pfcl, BT, C4, C_, FUSE_GELU);

        gemm_hmma64<<<dim3(C_ / 128, BT / 64), 256, G64_TOTAL>>>(
            pfch, pfcl, pwmh + (size_t)l * C4 * C_, pwml + (size_t)l * C4 * C_,
            mproj_b + (size_t)l * C_, px, px, BT, C_, C4, FUSE_RES);
    }

    layernorm_split<<<BT, 192>>>(px, lnf_w, lnf_b, plnh, plnl);

    int nbx = (V_ + 127) / 128;
    gemm_hmma<<<dim3(nbx, BT / 128), 256, GSM_TOTAL>>>(
        plnh, plnl, pteh, ptel, nullptr, nullptr, logits, nullptr, nullptr, BT, V_, C_, FUSE_NONE);

    loss_rows<<<BT, 256>>>(logits, targets, pnll, pvalid);

    int loss_idx = -1;
    if ((long long)out_size == BTV + 1) loss_idx = (int)BTV;
    else if (out_size == 1)             loss_idx = 0;
    if (loss_idx >= 0) finalize_loss<<<1, 256>>>(pnll, pvalid, (float*)d_out, loss_idx);
}

// round 15
// speedup vs baseline: 1.0122x; 1.0122x over previous
#include <cuda_runtime.h>
#include <cuda_bf16.h>
#include <math.h>
#include <stdint.h>

#define B_  2
#define T_  1024
#define C_  768
#define L_  12
#define H_  12
#define V_  50257
#define D_  64
#define BT  (B_*T_)          // 2048
#define C3  (3*C_)           // 2304
#define C4  (4*C_)           // 3072

typedef __nv_bfloat16 bf16;

// ---------------- scratch (device globals) ----------------
__device__ float g_x  [BT*C_];
__device__ float g_logits_fb[(size_t)BT*V_];
__device__ float g_nll[BT];
__device__ int   g_valid[BT];

// split-bf16 activations
__device__ bf16 g_lnh[BT*C_],  g_lnl[BT*C_];
__device__ bf16 g_qkvh[BT*C3], g_qkvl[BT*C3];
__device__ bf16 g_yh[BT*C_],   g_yl[BT*C_];
__device__ bf16 g_fch[BT*C4],  g_fcl[BT*C4];

// split-bf16 weights
__device__ bf16 g_wqkv_h[(size_t)L_*C_*C3], g_wqkv_l[(size_t)L_*C_*C3];
__device__ bf16 g_wapr_h[(size_t)L_*C_*C_], g_wapr_l[(size_t)L_*C_*C_];
__device__ bf16 g_wfc_h [(size_t)L_*C_*C4], g_wfc_l [(size_t)L_*C_*C4];
__device__ bf16 g_wmp_h [(size_t)L_*C4*C_], g_wmp_l [(size_t)L_*C4*C_];
__device__ bf16 g_wte_h [(size_t)V_*C_],    g_wte_l [(size_t)V_*C_];

// ---------------- ptx helpers ----------------
__device__ __forceinline__ uint32_t smem_u32(const void* p) {
    uint32_t a;
    asm("{ .reg .u64 t; cvta.to.shared.u64 t, %1; cvt.u32.u64 %0, t; }" : "=r"(a) : "l"(p));
    return a;
}
template<int N> __device__ __forceinline__ void cp_wait() {
    asm volatile("cp.async.wait_group %0;" :: "n"(N) : "memory");
}
__device__ __forceinline__ void cp_commit() {
    asm volatile("cp.async.commit_group;" ::: "memory");
}
__device__ __forceinline__ void cp16(uint32_t dst, const void* src, int sz) {
    asm volatile("cp.async.cg.shared.global [%0], [%1], 16, %2;"
                 :: "r"(dst), "l"(src), "r"(sz) : "memory");
}
__device__ __forceinline__ void ldsm4(uint32_t* r, uint32_t a) {
    asm volatile("ldmatrix.sync.aligned.m8n8.x4.shared.b16 {%0,%1,%2,%3}, [%4];"
                 : "=r"(r[0]), "=r"(r[1]), "=r"(r[2]), "=r"(r[3]) : "r"(a));
}
__device__ __forceinline__ void ldsm2t(uint32_t* r, uint32_t a) {
    asm volatile("ldmatrix.sync.aligned.m8n8.x2.trans.shared.b16 {%0,%1}, [%2];"
                 : "=r"(r[0]), "=r"(r[1]) : "r"(a));
}
__device__ __forceinline__ void mma16816(float* d, const uint32_t* a, const uint32_t* b) {
    asm volatile("mma.sync.aligned.m16n8k16.row.col.f32.bf16.bf16.f32 "
                 "{%0,%1,%2,%3}, {%4,%5,%6,%7}, {%8,%9}, {%0,%1,%2,%3};"
                 : "+f"(d[0]), "+f"(d[1]), "+f"(d[2]), "+f"(d[3])
                 : "r"(a[0]), "r"(a[1]), "r"(a[2]), "r"(a[3]), "r"(b[0]), "r"(b[1]));
}
__device__ __forceinline__ uint32_t pack_bf2(float a, float b) {
    __nv_bfloat162 t = __floats2bfloat162_rn(a, b);
    return *(uint32_t*)&t;
}
__device__ __forceinline__ uint32_t pack2(bf16 a, bf16 b) {
    return (uint32_t)(*(uint16_t*)&a) | ((uint32_t)(*(uint16_t*)&b) << 16);
}

__device__ __forceinline__ float gelu_f(float x) {
    const float k = 0.7978845608028654f;
    float x3 = x * x * x;
    return 0.5f * x * (1.0f + tanhf(k * (x + 0.044715f * x3)));
}

// ---------------- conversion kernels (weights only, vectorized) ------------
__global__ void convert_split(const float* __restrict__ in, bf16* __restrict__ hi,
                              bf16* __restrict__ lo, int n4) {
    int i = blockIdx.x * blockDim.x + threadIdx.x;
    int stride = gridDim.x * blockDim.x;
    const float4* in4 = (const float4*)in;
    uint2* hi2 = (uint2*)hi;
    uint2* lo2 = (uint2*)lo;
    for (; i < n4; i += stride) {
        float4 v = in4[i];
        bf16 h0 = __float2bfloat16_rn(v.x), h1 = __float2bfloat16_rn(v.y);
        bf16 h2 = __float2bfloat16_rn(v.z), h3 = __float2bfloat16_rn(v.w);
        hi2[i] = make_uint2(pack2(h0, h1), pack2(h2, h3));
        lo2[i] = make_uint2(pack_bf2(v.x - __bfloat162float(h0), v.y - __bfloat162float(h1)),
                            pack_bf2(v.z - __bfloat162float(h2), v.w - __bfloat162float(h3)));
    }
}

// in: [K,N] row-major per layer -> out: [N,K] split, 64k x 32n tiles
__global__ void transpose_split(const float* __restrict__ in, bf16* __restrict__ hi,
                                bf16* __restrict__ lo, int K, int N) {
    int l = blockIdx.z;
    in += (size_t)l * K * N;
    hi += (size_t)l * K * N;
    lo += (size_t)l * K * N;
    __shared__ float t[64][33];
    int n0 = blockIdx.x * 32, k0 = blockIdx.y * 64;
    #pragma unroll
    for (int i = 0; i < 8; i++) {
        int k = threadIdx.y + i * 8;
        t[k][threadIdx.x] = in[(size_t)(k0 + k) * N + n0 + threadIdx.x];
    }
    __syncthreads();
    #pragma unroll
    for (int i = 0; i < 4; i++) {
        int n = threadIdx.y + i * 8;
        float a = t[2 * threadIdx.x][n], c = t[2 * threadIdx.x + 1][n];
        bf16 ha = __float2bfloat16_rn(a), hc = __float2bfloat16_rn(c);
        size_t o = (size_t)(n0 + n) * K + k0 + 2 * threadIdx.x;
        *(uint32_t*)(hi + o) = pack2(ha, hc);
        *(uint32_t*)(lo + o) = pack_bf2(a - __bfloat162float(ha), c - __bfloat162float(hc));
    }
}

// ---------------- HMMA split-bf16 GEMM (3-stage, BM=128) --------------------
#define FUSE_NONE 0
#define FUSE_RES  1
#define FUSE_GELU 2
#define GSTG 32768
#define GSM_TOTAL (3*GSTG)

__device__ __forceinline__ uint32_t swoff(int r, int c) {
    return (uint32_t)(r * 64 + ((c ^ ((r >> 1) & 3)) << 4));
}

__global__ __launch_bounds__(256)
void gemm_hmma(const bf16* __restrict__ Ah, const bf16* __restrict__ Al,
               const bf16* __restrict__ Bh, const bf16* __restrict__ Bl,
               const float* __restrict__ bias, const float* __restrict__ res,
               float* __restrict__ Cm, bf16* __restrict__ OutH, bf16* __restrict__ OutL,
               int M, int N, int K, int fuse) {
    extern __shared__ char smem[];
    uint32_t sb = smem_u32(smem);
    int tid = threadIdx.x, lane = tid & 31, w = tid >> 5;
    int wm0 = (w & 3) * 32, wn0 = (w >> 2) * 64;
    int m0 = blockIdx.y * 128, n0 = blockIdx.x * 128;

    float acc[2][8][4];
    #pragma unroll
    for (int i = 0; i < 2; i++)
        #pragma unroll
        for (int j = 0; j < 8; j++)
            #pragma unroll
            for (int k = 0; k < 4; k++) acc[i][j][k] = 0.f;

    int cr = tid >> 2, cb = tid & 3;
    int nch = K >> 5;
    int rowoff = (lane & 7) + ((lane >> 3) & 1) * 8;
    int cbh = lane >> 4;

    auto prefetch = [&](int ch, uint32_t base) {
        int k0 = ch * 32;
        #pragma unroll
        for (int i = 0; i < 2; i++) {
            int r = cr + i * 64;
            uint32_t d = swoff(r, cb);
            size_t ao = (size_t)(m0 + r) * K + k0 + cb * 8;
            cp16(base + d, Ah + ao, 16);
            cp16(base + 8192 + d, Al + ao, 16);
            int nr = n0 + r;
            int nc = nr < N ? nr : (N - 1);
            int sz = nr < N ? 16 : 0;
            size_t bo = (size_t)nc * K + k0 + cb * 8;
            cp16(base + 16384 + d, Bh + bo, sz);
            cp16(base + 24576 + d, Bl + bo, sz);
        }
    };

    prefetch(0, sb); cp_commit();
    if (nch > 1) prefetch(1, sb + GSTG);
    cp_commit();

    int stage = 0, pstage = 2;
    for (int ch = 0; ch < nch; ch++) {
        cp_wait<1>();
        __syncthreads();
        if (ch + 2 < nch) prefetch(ch + 2, sb + pstage * GSTG);
        cp_commit();

        uint32_t aB = sb + stage * GSTG;
        uint32_t bB = aB + 16384;
        #pragma unroll
        for (int ks = 0; ks < 2; ks++) {
            uint32_t ah[2][4], al[2][4];
            #pragma unroll
            for (int mi = 0; mi < 2; mi++) {
                int row = wm0 + mi * 16 + rowoff;
                uint32_t ad = aB + (uint32_t)(row * 64) +
                              (uint32_t)((((2 * ks + cbh) ^ ((row >> 1) & 3))) << 4);
                ldsm4(ah[mi], ad);
                ldsm4(al[mi], ad + 8192);
            }
            uint32_t bh[8][2], bl[8][2];
            #pragma unroll
            for (int nj = 0; nj < 4; nj++) {
                int row = wn0 + nj * 16 + rowoff;
                uint32_t bd = bB + (uint32_t)(row * 64) +
                              (uint32_t)((((2 * ks + cbh) ^ ((row >> 1) & 3))) << 4);
                uint32_t q[4];
                ldsm4(q, bd);
                bh[2 * nj][0] = q[0]; bh[2 * nj][1] = q[2];
                bh[2 * nj + 1][0] = q[1]; bh[2 * nj + 1][1] = q[3];
                ldsm4(q, bd + 8192);
                bl[2 * nj][0] = q[0]; bl[2 * nj][1] = q[2];
                bl[2 * nj + 1][0] = q[1]; bl[2 * nj + 1][1] = q[3];
            }
            #pragma unroll
            for (int mi = 0; mi < 2; mi++)
                #pragma unroll
                for (int ni = 0; ni < 8; ni++) {
                    mma16816(acc[mi][ni], ah[mi], bh[ni]);
                    mma16816(acc[mi][ni], ah[mi], bl[ni]);
                    mma16816(acc[mi][ni], al[mi], bh[ni]);
                }
        }
        stage = (stage == 2) ? 0 : stage + 1;
        pstage = (pstage == 2) ? 0 : pstage + 1;
    }

    int r0 = lane >> 2, c0 = (lane & 3) * 2;
    bool vec_ok = (n0 + 128 <= N) && ((N & 1) == 0);
    #pragma unroll
    for (int mi = 0; mi < 2; mi++) {
        #pragma unroll
        for (int ni = 0; ni < 8; ni++) {
            int gr = m0 + wm0 + mi * 16 + r0;
            int gc = n0 + wn0 + ni * 8 + c0;
            float v0 = acc[mi][ni][0], v1 = acc[mi][ni][1];
            float v2 = acc[mi][ni][2], v3 = acc[mi][ni][3];
            if (vec_ok) {
                if (bias) { float b0 = bias[gc], b1 = bias[gc + 1]; v0 += b0; v1 += b1; v2 += b0; v3 += b1; }
                if (fuse == FUSE_RES) {
                    const float* r1p = res + (size_t)gr * N + gc;
                    const float* r2p = res + (size_t)(gr + 8) * N + gc;
                    v0 += r1p[0]; v1 += r1p[1]; v2 += r2p[0]; v3 += r2p[1];
                } else if (fuse == FUSE_GELU) {
                    v0 = gelu_f(v0); v1 = gelu_f(v1); v2 = gelu_f(v2); v3 = gelu_f(v3);
                }
                if (OutH) {
                    bf16 h0 = __float2bfloat16_rn(v0), h1 = __float2bfloat16_rn(v1);
                    bf16 h2 = __float2bfloat16_rn(v2), h3 = __float2bfloat16_rn(v3);
                    *(uint32_t*)(OutH + (size_t)gr * N + gc)       = pack2(h0, h1);
                    *(uint32_t*)(OutH + (size_t)(gr + 8) * N + gc) = pack2(h2, h3);
                    *(uint32_t*)(OutL + (size_t)gr * N + gc)       = pack_bf2(v0 - __bfloat162float(h0), v1 - __bfloat162float(h1));
                    *(uint32_t*)(OutL + (size_t)(gr + 8) * N + gc) = pack_bf2(v2 - __bfloat162float(h2), v3 - __bfloat162float(h3));
                } else {
                    *(float2*)(Cm + (size_t)gr * N + gc)       = make_float2(v0, v1);
                    *(float2*)(Cm + (size_t)(gr + 8) * N + gc) = make_float2(v2, v3);
                }
            } else {
                // scalar/ragged path (lm-head: N odd). float2 when 8B-aligned
                // ((gr*N + gc) even; gc always even so parity == gr*N parity).
                if (gc + 1 < N) {
                    float b0 = bias ? bias[gc] : 0.f;
                    float b1 = bias ? bias[gc + 1] : 0.f;
                    float a0 = v0 + b0, a1 = v1 + b1, a2 = v2 + b0, a3 = v3 + b1;
                    if (fuse == FUSE_RES) {
                        a0 += res[(size_t)gr * N + gc];     a1 += res[(size_t)gr * N + gc + 1];
                        a2 += res[(size_t)(gr + 8) * N + gc]; a3 += res[(size_t)(gr + 8) * N + gc + 1];
                    } else if (fuse == FUSE_GELU) {
                        a0 = gelu_f(a0); a1 = gelu_f(a1); a2 = gelu_f(a2); a3 = gelu_f(a3);
                    }
                    size_t i0 = (size_t)gr * N + gc;
                    size_t i1 = (size_t)(gr + 8) * N + gc;
                    if ((i0 & 1) == 0) *(float2*)(Cm + i0) = make_float2(a0, a1);
                    else { Cm[i0] = a0; Cm[i0 + 1] = a1; }
                    if ((i1 & 1) == 0) *(float2*)(Cm + i1) = make_float2(a2, a3);
                    else { Cm[i1] = a2; Cm[i1 + 1] = a3; }
                } else if (gc < N) {
                    float b0 = bias ? bias[gc] : 0.f;
                    float a0 = v0 + b0, a2 = v2 + b0;
                    if (fuse == FUSE_RES) { a0 += res[(size_t)gr * N + gc]; a2 += res[(size_t)(gr + 8) * N + gc]; }
                    else if (fuse == FUSE_GELU) { a0 = gelu_f(a0); a2 = gelu_f(a2); }
                    Cm[(size_t)gr * N + gc] = a0;
                    Cm[(size_t)(gr + 8) * N + gc] = a2;
                }
            }
        }
    }
}

// ---------------- HMMA split-bf16 GEMM (BM=64 variant, N%128==0) ------------
#define G64STG 24576
#define G64_TOTAL (3*G64STG)

__global__ __launch_bounds__(256)
void gemm_hmma64(const bf16* __restrict__ Ah, const bf16* __restrict__ Al,
                 const bf16* __restrict__ Bh, const bf16* __restrict__ Bl,
                 const float* __restrict__ bias, const float* __restrict__ res,
                 float* __restrict__ Cm, int M, int N, int K, int fuse) {
    extern __shared__ char smem[];
    uint32_t sb = smem_u32(smem);
    int tid = threadIdx.x, lane = tid & 31, w = tid >> 5;
    int wm0 = (w & 3) * 16, wn0 = (w >> 2) * 64;
    int m0 = blockIdx.y * 64, n0 = blockIdx.x * 128;

    float acc[8][4];
    #pragma unroll
    for (int j = 0; j < 8; j++)
        #pragma unroll
        for (int k = 0; k < 4; k++) acc[j][k] = 0.f;

    int cr = tid >> 2, cb = tid & 3;
    int nch = K >> 5;
    int rowoff = (lane & 7) + ((lane >> 3) & 1) * 8;
    int cbh = lane >> 4;

    auto prefetch = [&](int ch, uint32_t base) {
        int k0 = ch * 32;
        {
            int r = cr;
            uint32_t d = swoff(r, cb);
            size_t ao = (size_t)(m0 + r) * K + k0 + cb * 8;
            cp16(base + d, Ah + ao, 16);
            cp16(base + 4096 + d, Al + ao, 16);
        }
        #pragma unroll
        for (int i = 0; i < 2; i++) {
            int r = cr + i * 64;
            uint32_t d = swoff(r, cb);
            size_t bo = (size_t)(n0 + r) * K + k0 + cb * 8;
            cp16(base + 8192 + d, Bh + bo, 16);
            cp16(base + 16384 + d, Bl + bo, 16);
        }
    };

    prefetch(0, sb); cp_commit();
    if (nch > 1) prefetch(1, sb + G64STG);
    cp_commit();

    int stage = 0, pstage = 2;
    for (int ch = 0; ch < nch; ch++) {
        cp_wait<1>();
        __syncthreads();
        if (ch + 2 < nch) prefetch(ch + 2, sb + pstage * G64STG);
        cp_commit();

        uint32_t aB = sb + stage * G64STG;
        uint32_t bB = aB + 8192;
        #pragma unroll
        for (int ks = 0; ks < 2; ks++) {
            uint32_t ah[4], al[4];
            {
                int row = wm0 + rowoff;
                uint32_t ad = aB + (uint32_t)(row * 64) +
                              (uint32_t)((((2 * ks + cbh) ^ ((row >> 1) & 3))) << 4);
                ldsm4(ah, ad);
                ldsm4(al, ad + 4096);
            }
            uint32_t bh[8][2], bl[8][2];
            #pragma unroll
            for (int nj = 0; nj < 4; nj++) {
                int row = wn0 + nj * 16 + rowoff;
                uint32_t bd = bB + (uint32_t)(row * 64) +
                              (uint32_t)((((2 * ks + cbh) ^ ((row >> 1) & 3))) << 4);
                uint32_t q[4];
                ldsm4(q, bd);
                bh[2 * nj][0] = q[0]; bh[2 * nj][1] = q[2];
                bh[2 * nj + 1][0] = q[1]; bh[2 * nj + 1][1] = q[3];
                ldsm4(q, bd + 8192);
                bl[2 * nj][0] = q[0]; bl[2 * nj][1] = q[2];
                bl[2 * nj + 1][0] = q[1]; bl[2 * nj + 1][1] = q[3];
            }
            #pragma unroll
            for (int ni = 0; ni < 8; ni++) {
                mma16816(acc[ni], ah, bh[ni]);
                mma16816(acc[ni], ah, bl[ni]);
                mma16816(acc[ni], al, bh[ni]);
            }
        }
        stage = (stage == 2) ? 0 : stage + 1;
        pstage = (pstage == 2) ? 0 : pstage + 1;
    }

    int r0 = lane >> 2, c0 = (lane & 3) * 2;
    #pragma unroll
    for (int ni = 0; ni < 8; ni++) {
        int gr = m0 + wm0 + r0;
        int gc = n0 + wn0 + ni * 8 + c0;
        float v0 = acc[ni][0], v1 = acc[ni][1];
        float v2 = acc[ni][2], v3 = acc[ni][3];
        if (bias) { float b0 = bias[gc], b1 = bias[gc + 1]; v0 += b0; v1 += b1; v2 += b0; v3 += b1; }
        if (fuse == FUSE_RES) {
            const float* r1p = res + (size_t)gr * N + gc;
            const float* r2p = res + (size_t)(gr + 8) * N + gc;
            v0 += r1p[0]; v1 += r1p[1]; v2 += r2p[0]; v3 += r2p[1];
        } else if (fuse == FUSE_GELU) {
            v0 = gelu_f(v0); v1 = gelu_f(v1); v2 = gelu_f(v2); v3 = gelu_f(v3);
        }
        *(float2*)(Cm + (size_t)gr * N + gc)       = make_float2(v0, v1);
        *(float2*)(Cm + (size_t)(gr + 8) * N + gc) = make_float2(v2, v3);
    }
}

// ---------------- flash attention (64-row Q tiles, validated R13 version) ---
#define FPAD 72
#define FARR 9216
#define FSTG (4*FARR)
#define FSM_TOTAL (2*FSTG)
__global__ __launch_bounds__(128)
void flash_attn(const bf16* __restrict__ qkvh, const bf16* __restrict__ qkvl,
                bf16* __restrict__ yh, bf16* __restrict__ yl) {
    extern __shared__ char fsm[];
    uint32_t sbase = smem_u32(fsm);
    int qt = gridDim.x - 1 - blockIdx.x;
    int bh = blockIdx.y;
    int b = bh / H_, h = bh % H_;
    int tid = threadIdx.x, w = tid >> 5, lane = tid & 31;
    int g = lane >> 2, tg = lane & 3;
    int t0 = qt * 64;
    int row = t0 + w * 16 + g;
    size_t grA = (size_t)(b * T_ + row) * C3 + h * D_;
    size_t grB = grA + (size_t)8 * C3;

    auto pf = [&](int st, uint32_t base) {
        int s0 = st * 64;
        #pragma unroll
        for (int i = 0; i < 8; i++) {
            int e = tid + i * 128;
            int r = (e >> 3) & 63, j = e & 7;
            int isV = (e >= 512);
            size_t gsrc = (size_t)(b * T_ + s0 + r) * C3 + C_ + (isV ? C_ : 0) + h * D_ + j * 8;
            uint32_t d = base + (uint32_t)(isV ? 2 * FARR : 0) + (uint32_t)(r * 144 + j * 16);
            cp16(d, qkvh + gsrc, 16);
            cp16(d + FARR, qkvl + gsrc, 16);
        }
    };

    uint32_t qah[4][4], qal[4][4];
    #pragma unroll
    for (int kk = 0; kk < 4; kk++) {
        int k = kk * 16 + tg * 2;
        qah[kk][0] = *(const uint32_t*)(qkvh + grA + k);
        qah[kk][1] = *(const uint32_t*)(qkvh + grB + k);
        qah[kk][2] = *(const uint32_t*)(qkvh + grA + k + 8);
        qah[kk][3] = *(const uint32_t*)(qkvh + grB + k + 8);
        qal[kk][0] = *(const uint32_t*)(qkvl + grA + k);
        qal[kk][1] = *(const uint32_t*)(qkvl + grB + k);
        qal[kk][2] = *(const uint32_t*)(qkvl + grA + k + 8);
        qal[kk][3] = *(const uint32_t*)(qkvl + grB + k + 8);
    }

    pf(0, sbase);
    cp_commit();

    float O[8][4];
    #pragma unroll
    for (int i = 0; i < 8; i++)
        #pragma unroll
        for (int j = 0; j < 4; j++) O[i][j] = 0.f;
    float m0 = -1e30f, m1 = -1e30f, l0 = 0.f, l1 = 0.f;

    for (int st = 0; st <= qt; st++) {
        int s0 = st * 64;
        cp_wait<0>();
        __syncthreads();
        if (st + 1 <= qt) { pf(st + 1, sbase + ((st + 1) & 1) * FSTG); cp_commit(); }

        uint32_t stg = sbase + (st & 1) * FSTG;
        const bf16* kh = (const bf16*)(fsm + (st & 1) * FSTG);
        const bf16* kl = kh + FARR / 2;

        float S[8][4];
        #pragma unroll
        for (int nf = 0; nf < 8; nf++) {
            S[nf][0] = S[nf][1] = S[nf][2] = S[nf][3] = 0.f;
            int n = nf * 8 + g;
            #pragma unroll
            for (int kk = 0; kk < 4; kk++) {
                int k = kk * 16 + tg * 2;
                uint32_t bfr[2], bfl[2];
                bfr[0] = *(const uint32_t*)&kh[n * FPAD + k];
                bfr[1] = *(const uint32_t*)&kh[n * FPAD + k + 8];
                bfl[0] = *(const uint32_t*)&kl[n * FPAD + k];
                bfl[1] = *(const uint32_t*)&kl[n * FPAD + k + 8];
                mma16816(S[nf], qah[kk], bfr);
                mma16816(S[nf], qah[kk], bfl);
                mma16816(S[nf], qal[kk], bfr);
            }
        }

        bool diag = (st == qt);
        #pragma unroll
        for (int nf = 0; nf < 8; nf++) {
            int cbase = s0 + nf * 8 + tg * 2;
            #pragma unroll
            for (int j = 0; j < 4; j++) {
                S[nf][j] *= 0.125f;
                if (diag) {
                    int cc = cbase + (j & 1);
                    int rr = row + (j >> 1) * 8;
                    if (cc > rr) S[nf][j] = -1e30f;
                }
            }
        }

        float rm0 = -1e30f, rm1 = -1e30f;
        #pragma unroll
        for (int nf = 0; nf < 8; nf++) {
            rm0 = fmaxf(rm0, fmaxf(S[nf][0], S[nf][1]));
            rm1 = fmaxf(rm1, fmaxf(S[nf][2], S[nf][3]));
        }
        rm0 = fmaxf(rm0, __shfl_xor_sync(0xffffffffu, rm0, 1));
        rm0 = fmaxf(rm0, __shfl_xor_sync(0xffffffffu, rm0, 2));
        rm1 = fmaxf(rm1, __shfl_xor_sync(0xffffffffu, rm1, 1));
        rm1 = fmaxf(rm1, __shfl_xor_sync(0xffffffffu, rm1, 2));
        float mn0 = fmaxf(m0, rm0), mn1 = fmaxf(m1, rm1);
        float cr0 = __expf(m0 - mn0), cr1 = __expf(m1 - mn1);
        m0 = mn0; m1 = mn1;

        uint32_t ph[8][2], pl[8][2];
        float ls0 = 0.f, ls1 = 0.f;
        #pragma unroll
        for (int nf = 0; nf < 8; nf++) {
            float p0 = __expf(S[nf][0] - m0), p1 = __expf(S[nf][1] - m0);
            float p2 = __expf(S[nf][2] - m1), p3 = __expf(S[nf][3] - m1);
            ls0 += p0 + p1; ls1 += p2 + p3;
            bf16 h0 = __float2bfloat16_rn(p0), h1 = __float2bfloat16_rn(p1);
            bf16 h2 = __float2bfloat16_rn(p2), h3 = __float2bfloat16_rn(p3);
            ph[nf][0] = pack2(h0, h1);
            ph[nf][1] = pack2(h2, h3);
            pl[nf][0] = pack_bf2(p0 - __bfloat162float(h0), p1 - __bfloat162float(h1));
            pl[nf][1] = pack_bf2(p2 - __bfloat162float(h2), p3 - __bfloat162float(h3));
        }
        l0 = l0 * cr0 + ls0;
        l1 = l1 * cr1 + ls1;
        #pragma unroll
        for (int nf = 0; nf < 8; nf++) {
            O[nf][0] *= cr0; O[nf][1] *= cr0;
            O[nf][2] *= cr1; O[nf][3] *= cr1;
        }

        uint32_t vhB = stg + 2 * FARR;
        int lrow = lane & 15;
        #pragma unroll
        for (int kk = 0; kk < 4; kk++) {
            uint32_t pah[4] = { ph[2*kk][0], ph[2*kk][1], ph[2*kk+1][0], ph[2*kk+1][1] };
            uint32_t pal[4] = { pl[2*kk][0], pl[2*kk][1], pl[2*kk+1][0], pl[2*kk+1][1] };
            uint32_t rbase = vhB + (uint32_t)((kk * 16 + lrow) * 144);
            #pragma unroll
            for (int nf = 0; nf < 8; nf++) {
                uint32_t addr = rbase + (uint32_t)(nf * 16);
                uint32_t vbh[2], vbl[2];
                ldsm2t(vbh, addr);
                ldsm2t(vbl, addr + FARR);
                mma16816(O[nf], pah, vbh);
                mma16816(O[nf], pah, vbl);
                mma16816(O[nf], pal, vbh);
            }
        }
    }

    l0 += __shfl_xor_sync(0xffffffffu, l0, 1);
    l0 += __shfl_xor_sync(0xffffffffu, l0, 2);
    l1 += __shfl_xor_sync(0xffffffffu, l1, 1);
    l1 += __shfl_xor_sync(0xffffffffu, l1, 2);
    float inv0 = 1.0f / l0, inv1 = 1.0f / l1;
    size_t yo0 = (size_t)(b * T_ + row) * C_ + h * D_;
    size_t yo1 = yo0 + (size_t)8 * C_;
    #pragma unroll
    for (int nf = 0; nf < 8; nf++) {
        int d = nf * 8 + tg * 2;
        float v0 = O[nf][0] * inv0, v1 = O[nf][1] * inv0;
        float v2 = O[nf][2] * inv1, v3 = O[nf][3] * inv1;
        bf16 h0 = __float2bfloat16_rn(v0), h1 = __float2bfloat16_rn(v1);
        bf16 h2 = __float2bfloat16_rn(v2), h3 = __float2bfloat16_rn(v3);
        *(uint32_t*)(yh + yo0 + d) = pack2(h0, h1);
        *(uint32_t*)(yh + yo1 + d) = pack2(h2, h3);
        *(uint32_t*)(yl + yo0 + d) = pack_bf2(v0 - __bfloat162float(h0), v1 - __bfloat162float(h1));
        *(uint32_t*)(yl + yo1 + d) = pack_bf2(v2 - __bfloat162float(h2), v3 - __bfloat162float(h3));
    }
}

// ---------------- embedding (vectorized) ----------------
__global__ void embed_k(const int* __restrict__ idx, const float* __restrict__ wte,
                        const float* __restrict__ wpe, float* __restrict__ x) {
    int row = blockIdx.x;
    int t = row % T_;
    int tok = idx[row];
    const float4* pe = (const float4*)(wpe + (size_t)t * C_);
    const float4* pw = (const float4*)(wte + (size_t)tok * C_);
    float4* po = (float4*)(x + (size_t)row * C_);
    int i = threadIdx.x;
    float4 a = pw[i], c = pe[i];
    po[i] = make_float4(a.x + c.x, a.y + c.y, a.z + c.z, a.w + c.w);
}

// ---------------- layernorm -> split bf16 (192 thr, float4, 1-pass) --------
__global__ __launch_bounds__(192)
void layernorm_split(const float* __restrict__ x, const float* __restrict__ w,
                     const float* __restrict__ b, bf16* __restrict__ oh,
                     bf16* __restrict__ ol) {
    int row = blockIdx.x;
    int tid = threadIdx.x;
    const float4* px = (const float4*)(x + (size_t)row * C_);
    float4 v = px[tid];
    float s = v.x + v.y + v.z + v.w;
    float q = v.x * v.x + v.y * v.y + v.z * v.z + v.w * v.w;
    #pragma unroll
    for (int o = 16; o; o >>= 1) {
        s += __shfl_xor_sync(0xffffffffu, s, o);
        q += __shfl_xor_sync(0xffffffffu, q, o);
    }
    __shared__ float ss[6], qq[6];
    if ((tid & 31) == 0) { ss[tid >> 5] = s; qq[tid >> 5] = q; }
    __syncthreads();
    s = ss[0] + ss[1] + ss[2] + ss[3] + ss[4] + ss[5];
    q = qq[0] + qq[1] + qq[2] + qq[3] + qq[4] + qq[5];
    float mean = s * (1.0f / C_);
    float var = q * (1.0f / C_) - mean * mean;
    float rstd = rsqrtf(var + 1e-5f);

    float4 w4 = ((const float4*)w)[tid];
    float4 b4 = ((const float4*)b)[tid];
    float o0 = (v.x - mean) * rstd * w4.x + b4.x;
    float o1 = (v.y - mean) * rstd * w4.y + b4.y;
    float o2 = (v.z - mean) * rstd * w4.z + b4.z;
    float o3 = (v.w - mean) * rstd * w4.w + b4.w;
    bf16 h0 = __float2bfloat16_rn(o0), h1 = __float2bfloat16_rn(o1);
    bf16 h2 = __float2bfloat16_rn(o2), h3 = __float2bfloat16_rn(o3);
    ((uint2*)(oh + (size_t)row * C_))[tid] = make_uint2(pack2(h0, h1), pack2(h2, h3));
    ((uint2*)(ol + (size_t)row * C_))[tid] =
        make_uint2(pack_bf2(o0 - __bfloat162float(h0), o1 - __bfloat162float(h1)),
                   pack_bf2(o2 - __bfloat162float(h2), o3 - __bfloat162float(h3)));
}

// ---------------- loss: single-pass online logsumexp ----------------
__global__ void loss_rows(const float* __restrict__ logits, const int* __restrict__ targets,
                          float* __restrict__ nll, int* __restrict__ valid) {
    int row = blockIdx.x;
    const float* p = logits + (size_t)row * V_;
    int tid = threadIdx.x;

    int pre = ((16 - (int)(((uintptr_t)p) & 15)) & 15) >> 2;
    if (pre > V_) pre = V_;
    const float4* p4 = (const float4*)(p + pre);
    int n4 = (V_ - pre) >> 2;
    int tail = pre + n4 * 4;

    float m = -INFINITY, s = 0.f;
    auto upd = [&](float v) {
        if (v <= m) s += __expf(v - m);
        else { s = s * __expf(m - v) + 1.0f; m = v; }
    };
    if (tid < pre) upd(p[tid]);
    for (int i = tid; i < n4; i += 256) {
        float4 v = p4[i];
        upd(v.x); upd(v.y); upd(v.z); upd(v.w);
    }
    for (int i = tail + tid; i < V_; i += 256) upd(p[i]);

    __shared__ float rm[256], rs[256];
    rm[tid] = m; rs[tid] = s; __syncthreads();
    for (int off = 128; off > 0; off >>= 1) {
        if (tid < off) {
            float m2 = rm[tid + off], s2 = rs[tid + off];
            float mm = fmaxf(rm[tid], m2);
            rs[tid] = rs[tid] * __expf(rm[tid] - mm) + s2 * __expf(m2 - mm);
            rm[tid] = mm;
        }
        __syncthreads();
    }

    if (tid == 0) {
        int t = targets[row];
        if (t != -1) {
            nll[row] = -(p[t] - rm[0] - logf(rs[0]));
            valid[row] = 1;
        } else {
            nll[row] = 0.f;
            valid[row] = 0;
        }
    }
}

__global__ void finalize_loss(const float* __restrict__ nll, const int* __restrict__ valid,
                              float* out, int loss_idx) {
    __shared__ float red[256];
    __shared__ int cnt[256];
    int tid = threadIdx.x;
    float s = 0.f; int c = 0;
    for (int i = tid; i < BT; i += 256) { s += nll[i]; c += valid[i]; }
    red[tid] = s; cnt[tid] = c; __syncthreads();
    for (int off = 128; off > 0; off >>= 1) {
        if (tid < off) { red[tid] += red[tid + off]; cnt[tid] += cnt[tid + off]; }
        __syncthreads();
    }
    if (tid == 0) {
        int v = cnt[0]; if (v < 1) v = 1;
        out[loss_idx] = red[0] / (float)v;
    }
}

// ---------------- host launcher ----------------
extern "C" void kernel_launch(void* const* d_in, const int* in_sizes, int n_in,
                              void* d_out, int out_size) {
    const int*   idx     = (const int*)  d_in[0];
    const int*   targets = (const int*)  d_in[1];
    const float* wte     = (const float*)d_in[2];
    const float* wpe     = (const float*)d_in[3];
    const float* ln1_w   = (const float*)d_in[4];
    const float* ln1_b   = (const float*)d_in[5];
    const float* attn_w  = (const float*)d_in[6];
    const float* attn_b  = (const float*)d_in[7];
    const float* aproj_w = (const float*)d_in[8];
    const float* aproj_b = (const float*)d_in[9];
    const float* ln2_w   = (const float*)d_in[10];
    const float* ln2_b   = (const float*)d_in[11];
    const float* fc_w    = (const float*)d_in[12];
    const float* fc_b    = (const float*)d_in[13];
    const float* mproj_w = (const float*)d_in[14];
    const float* mproj_b = (const float*)d_in[15];
    const float* lnf_w   = (const float*)d_in[16];
    const float* lnf_b   = (const float*)d_in[17];

    float *px, *pfb, *pnll;
    int *pvalid;
    bf16 *plnh, *plnl, *pqkvh, *pqkvl, *pyh, *pyl, *pfch, *pfcl;
    bf16 *pwqh, *pwql, *pwah, *pwal, *pwfh, *pwfl, *pwmh, *pwml, *pteh, *ptel;
    cudaGetSymbolAddress((void**)&px,    g_x);
    cudaGetSymbolAddress((void**)&pfb,   g_logits_fb);
    cudaGetSymbolAddress((void**)&pnll,  g_nll);
    cudaGetSymbolAddress((void**)&pvalid,g_valid);
    cudaGetSymbolAddress((void**)&plnh,  g_lnh);
    cudaGetSymbolAddress((void**)&plnl,  g_lnl);
    cudaGetSymbolAddress((void**)&pqkvh, g_qkvh);
    cudaGetSymbolAddress((void**)&pqkvl, g_qkvl);
    cudaGetSymbolAddress((void**)&pyh,   g_yh);
    cudaGetSymbolAddress((void**)&pyl,   g_yl);
    cudaGetSymbolAddress((void**)&pfch,  g_fch);
    cudaGetSymbolAddress((void**)&pfcl,  g_fcl);
    cudaGetSymbolAddress((void**)&pwqh,  g_wqkv_h);
    cudaGetSymbolAddress((void**)&pwql,  g_wqkv_l);
    cudaGetSymbolAddress((void**)&pwah,  g_wapr_h);
    cudaGetSymbolAddress((void**)&pwal,  g_wapr_l);
    cudaGetSymbolAddress((void**)&pwfh,  g_wfc_h);
    cudaGetSymbolAddress((void**)&pwfl,  g_wfc_l);
    cudaGetSymbolAddress((void**)&pwmh,  g_wmp_h);
    cudaGetSymbolAddress((void**)&pwml,  g_wmp_l);
    cudaGetSymbolAddress((void**)&pteh,  g_wte_h);
    cudaGetSymbolAddress((void**)&ptel,  g_wte_l);

    cudaFuncSetAttribute(gemm_hmma,   cudaFuncAttributeMaxDynamicSharedMemorySize, GSM_TOTAL);
    cudaFuncSetAttribute(gemm_hmma64, cudaFuncAttributeMaxDynamicSharedMemorySize, G64_TOTAL);
    cudaFuncSetAttribute(flash_attn,  cudaFuncAttributeMaxDynamicSharedMemorySize, FSM_TOTAL);

    static cudaStream_t s2 = nullptr;
    static cudaEvent_t  ev_fork = nullptr, ev_join = nullptr;
    if (!s2) {
        cudaStreamCreateWithFlags(&s2, cudaStreamNonBlocking);
        cudaEventCreateWithFlags(&ev_fork, cudaEventDisableTiming);
        cudaEventCreateWithFlags(&ev_join, cudaEventDisableTiming);
    }

    const long long BTV = (long long)BT * V_;
    float* logits = ((long long)out_size >= BTV) ? (float*)d_out : pfb;

    dim3 tb(32, 8);

    cudaEventRecord(ev_fork, 0);
    cudaStreamWaitEvent(s2, ev_fork, 0);
    transpose_split<<<dim3(C_ / 32, C_ / 64, L_), tb, 0, s2>>>(aproj_w, pwah, pwal, C_, C_);
    transpose_split<<<dim3(C4 / 32, C_ / 64, L_), tb, 0, s2>>>(fc_w,    pwfh, pwfl, C_, C4);
    transpose_split<<<dim3(C_ / 32, C4 / 64, L_), tb, 0, s2>>>(mproj_w, pwmh, pwml, C4, C_);
    convert_split<<<4096, 256, 0, s2>>>(wte, pteh, ptel, (V_ * C_) / 4);
    cudaEventRecord(ev_join, s2);

    transpose_split<<<dim3(C3 / 32, C_ / 64, L_), tb>>>(attn_w, pwqh, pwql, C_, C3);
    embed_k<<<BT, 192>>>(idx, wte, wpe, px);

    for (int l = 0; l < L_; l++) {
        layernorm_split<<<BT, 192>>>(px, ln1_w + (size_t)l * C_, ln1_b + (size_t)l * C_, plnh, plnl);
        gemm_hmma<<<dim3(C3 / 128, BT / 128), 256, GSM_TOTAL>>>(
            plnh, plnl, pwqh + (size_t)l * C_ * C3, pwql + (size_t)l * C_ * C3,
            attn_b + (size_t)l * C3, nullptr, nullptr, pqkvh, pqkvl, BT, C3, C_, FUSE_NONE);

        flash_attn<<<dim3(T_ / 64, B_ * H_), 128, FSM_TOTAL>>>(pqkvh, pqkvl, pyh, pyl);

        if (l == 0) cudaStreamWaitEvent(0, ev_join, 0);

        gemm_hmma64<<<dim3(C_ / 128, BT / 64), 256, G64_TOTAL>>>(
            pyh, pyl, pwah + (size_t)l * C_ * C_, pwal + (size_t)l * C_ * C_,
            aproj_b + (size_t)l * C_, px, px, BT, C_, C_, FUSE_RES);

        layernorm_split<<<BT, 192>>>(px, ln2_w + (size_t)l * C_, ln2_b + (size_t)l * C_, plnh, plnl);
        gemm_hmma<<<dim3(C4 / 128, BT / 128), 256, GSM_TOTAL>>>(
            plnh, plnl, pwfh + (size_t)l * C_ * C4, pwfl + (size_t)l * C_ * C4,
            fc_b + (size_t)l * C4, nullptr, nullptr, pfch, pfcl, BT, C4, C_, FUSE_GELU);

        gemm_hmma64<<<dim3(C_ / 128, BT / 64), 256, G64_TOTAL>>>(
            pfch, pfcl, pwmh + (size_t)l * C4 * C_, pwml + (size_t)l * C4 * C_,
            mproj_b + (size_t)l * C_, px, px, BT, C_, C4, FUSE_RES);
    }

    layernorm_split<<<BT, 192>>>(px, lnf_w, lnf_b, plnh, plnl);

    int nbx = (V_ + 127) / 128;
    gemm_hmma<<<dim3(nbx, BT / 128), 256, GSM_TOTAL>>>(
        plnh, plnl, pteh, ptel, nullptr, nullptr, logits, nullptr, nullptr, BT, V_, C_, FUSE_NONE);

    loss_rows<<<BT, 256>>>(logits, targets, pnll, pvalid);

    int loss_idx = -1;
    if ((long long)out_size == BTV + 1) loss_idx = (int)BTV;
    else if (out_size == 1)             loss_idx = 0;
    if (loss_idx >= 0) finalize_loss<<<1, 256>>>(pnll, pvalid, (float*)d_out, loss_idx);
}